// round 2
// baseline (speedup 1.0000x reference)
#include <cuda_runtime.h>

// GaussianConvBlur: depthwise 7x7 conv (block-diagonal weight, identical
// perturbed Gaussian per channel) over [16,64,256,256] fp32.
//
// Strategy: f32x2 packed FMA (fma.rn.f32x2) -> 2 outputs per FFMA2 instr.
// Row-major shared tile, sliding-window over input rows with 7-slot
// accumulator ring, coalesced STG.64 stores.

#define NCH 64
#define IMG 256
#define KS  7
#define TILE_W 64
#define TILE_H 128
#define SM_ROWS (TILE_H + 6)   // 134
#define SM_COLS 72             // 70 used, padded to 72 (8B alignment, no conflicts)

typedef unsigned long long ull_t;

__device__ float g_w[NCH * KS * KS];   // effective per-channel 7x7 kernel

__device__ __forceinline__ ull_t pk2(float lo, float hi) {
    ull_t r;
    asm("mov.b64 %0, {%1, %2};" : "=l"(r) : "f"(lo), "f"(hi));
    return r;
}
__device__ __forceinline__ void fma2(ull_t& d, ull_t a, ull_t b) {
    asm("fma.rn.f32x2 %0, %1, %2, %0;" : "+l"(d) : "l"(a), "l"(b));
}

// ---------------------------------------------------------------------------
// Prologue: w_eff[c][j][k] = weight[c][c][j][k] + noise*(eps[j][k] - mean(eps))
// ---------------------------------------------------------------------------
__global__ void prep_weights(const float* __restrict__ weight,
                             const float* __restrict__ noise,
                             const float* __restrict__ eps) {
    int c = threadIdx.x;
    if (c >= NCH) return;
    float m = 0.f;
#pragma unroll
    for (int i = 0; i < 49; ++i) m += eps[i];
    m *= (1.0f / 49.0f);
    float nz = noise[0];
    const float* wp = weight + ((size_t)c * NCH + c) * 49;
#pragma unroll
    for (int i = 0; i < 49; ++i)
        g_w[c * 49 + i] = wp[i] + nz * (eps[i] - m);
}

// ---------------------------------------------------------------------------
// Main conv kernel. Grid: (4, 2, 1024). Block: 128 threads (4 warps).
// Warp w handles output rows [32w, 32w+32) of the 64x128 tile.
// Lane l handles output cols (2l, 2l+1) -> f32x2 accumulator.
// ---------------------------------------------------------------------------
__global__ __launch_bounds__(128, 3)
void conv7x7_kernel(const float* __restrict__ x, float* __restrict__ out) {
    __shared__ float sm[SM_ROWS][SM_COLS];

    const int tid   = threadIdx.x;
    const int plane = blockIdx.z;            // n*64 + ch
    const int ch    = plane & (NCH - 1);
    const int C0    = blockIdx.x * TILE_W;
    const int R0    = blockIdx.y * TILE_H;

    const float* in = x + (size_t)plane * (IMG * IMG);

    // ---- weights into packed (w,w) register pairs ----
    ull_t WW[49];
    {
        const float* wp = g_w + ch * 49;
#pragma unroll
        for (int i = 0; i < 49; ++i) {
            float w = __ldg(wp + i);
            WW[i] = pk2(w, w);
        }
    }

    // ---- stage input tile (with 3-halo, zero-padded at image borders) ----
    for (int i = tid; i < SM_ROWS * 70; i += 128) {
        int r  = i / 70;
        int c  = i - r * 70;
        int gr = R0 - 3 + r;
        int gc = C0 - 3 + c;
        float v = 0.f;
        if ((unsigned)gr < (unsigned)IMG && (unsigned)gc < (unsigned)IMG)
            v = in[gr * IMG + gc];
        sm[r][c] = v;
    }
    __syncthreads();

    const int wid   = tid >> 5;
    const int lane  = tid & 31;
    const int rbase = wid * 32;        // smem row base for this warp
    const int c2    = 2 * lane;        // smem col base (even -> 8B aligned)

    ull_t acc[7];
#pragma unroll
    for (int i = 0; i < 7; ++i) acc[i] = 0ull;

    float* outp = out + (size_t)plane * (IMG * IMG);

#pragma unroll
    for (int r = 0; r < 38; ++r) {
        // Aligned 8B loads covering smem cols [c2, c2+8)
        const float2* row = reinterpret_cast<const float2*>(&sm[rbase + r][c2]);
        float2 A0 = row[0];
        float2 A1 = row[1];
        float2 A2 = row[2];
        float2 A3 = row[3];

        ull_t P[7];
        P[0] = pk2(A0.x, A0.y);
        P[2] = pk2(A1.x, A1.y);
        P[4] = pk2(A2.x, A2.y);
        P[6] = pk2(A3.x, A3.y);
        P[1] = pk2(A0.y, A1.x);
        P[3] = pk2(A1.y, A2.x);
        P[5] = pk2(A2.y, A3.x);

#pragma unroll
        for (int j = 0; j < 7; ++j) {
            int y = r - j;                       // output row fed by this input row
            if (y < 0 || y >= 32) continue;      // compile-time dead-code
            ull_t* a = &acc[y % 7];
#pragma unroll
            for (int k = 0; k < 7; ++k)
                fma2(*a, P[k], WW[j * 7 + k]);
        }

        if (r >= 6) {                            // output row r-6 is complete
            int y  = r - 6;
            int gy = R0 + rbase + y;
            *reinterpret_cast<ull_t*>(outp + gy * IMG + C0 + c2) = acc[y % 7];
            acc[y % 7] = 0ull;
        }
    }
}

extern "C" void kernel_launch(void* const* d_in, const int* in_sizes, int n_in,
                              void* d_out, int out_size) {
    const float* x      = (const float*)d_in[0];  // [16,64,256,256]
    const float* weight = (const float*)d_in[1];  // [64,64,7,7]
    const float* noise  = (const float*)d_in[2];  // scalar
    const float* eps    = (const float*)d_in[3];  // [7,7]
    float* out = (float*)d_out;

    prep_weights<<<1, NCH>>>(weight, noise, eps);

    dim3 grid(IMG / TILE_W, IMG / TILE_H, 16 * NCH);   // (4, 2, 1024)
    conv7x7_kernel<<<grid, 128>>>(x, out);
}

// round 3
// speedup vs baseline: 1.2808x; 1.2808x over previous
#include <cuda_runtime.h>

// GaussianConvBlur: depthwise 7x7 conv (block-diagonal weight, identical
// perturbed Gaussian per channel) over [16,64,256,256] fp32.
//
// R3: f32x2 packed FMA + vectorized float4 staging + union-punned packing
//     + 4 CTAs/SM occupancy.

#define NCH 64
#define IMG 256
#define KS  7
#define TILE_W 64
#define TILE_H 128
#define SM_ROWS (TILE_H + 6)   // 134
#define SM_COLS 72             // window [C0-4, C0+68): 72 floats, float4-aligned

typedef unsigned long long ull_t;

__device__ float g_w[NCH * KS * KS];   // effective per-channel 7x7 kernel

union F2U { float2 f; ull_t u; };

__device__ __forceinline__ ull_t pk2(float lo, float hi) {
    ull_t r;
    asm("mov.b64 %0, {%1, %2};" : "=l"(r) : "f"(lo), "f"(hi));
    return r;
}
__device__ __forceinline__ void fma2(ull_t& d, ull_t a, ull_t b) {
    asm("fma.rn.f32x2 %0, %1, %2, %0;" : "+l"(d) : "l"(a), "l"(b));
}

// ---------------------------------------------------------------------------
// Prologue: w_eff[c][j][k] = weight[c][c][j][k] + noise*(eps[j][k] - mean(eps))
// ---------------------------------------------------------------------------
__global__ void prep_weights(const float* __restrict__ weight,
                             const float* __restrict__ noise,
                             const float* __restrict__ eps) {
    int c = threadIdx.x;
    if (c >= NCH) return;
    float m = 0.f;
#pragma unroll
    for (int i = 0; i < 49; ++i) m += eps[i];
    m *= (1.0f / 49.0f);
    float nz = noise[0];
    const float* wp = weight + ((size_t)c * NCH + c) * 49;
#pragma unroll
    for (int i = 0; i < 49; ++i)
        g_w[c * 49 + i] = wp[i] + nz * (eps[i] - m);
}

// ---------------------------------------------------------------------------
// Main conv kernel. Grid: (4, 2, 1024). Block: 128 threads (4 warps).
// Warp w handles output rows [32w, 32w+32) of the 64x128 tile.
// Lane l handles output cols (2l, 2l+1) -> f32x2 accumulator.
// smem col j holds input col C0-4+j; taps for lane's pair live at
// cols [c2+1, c2+8] -> 5 aligned LDS.64 at c2..c2+9, 4 cross-packs.
// ---------------------------------------------------------------------------
__global__ __launch_bounds__(128, 4)
void conv7x7_kernel(const float* __restrict__ x, float* __restrict__ out) {
    __shared__ float sm[SM_ROWS][SM_COLS];

    const int tid   = threadIdx.x;
    const int plane = blockIdx.z;            // n*64 + ch
    const int ch    = plane & (NCH - 1);
    const int C0    = blockIdx.x * TILE_W;
    const int R0    = blockIdx.y * TILE_H;

    const float* in = x + (size_t)plane * (IMG * IMG);

    // ---- weights into packed (w,w) register pairs ----
    ull_t WW[49];
    {
        const float* wp = g_w + ch * 49;
#pragma unroll
        for (int i = 0; i < 49; ++i) {
            float w = __ldg(wp + i);
            WW[i] = pk2(w, w);
        }
    }

    // ---- stage input tile: float4 window [C0-4, C0+68), zero-padded ----
    // 134 rows x 18 float4 = 2412 vectors; each is fully in-range or fully out.
    {
        const int NF4 = SM_ROWS * 18;
        for (int i = tid; i < NF4; i += 128) {
            int r  = i / 18;
            int f  = i - r * 18;
            int gr = R0 - 3 + r;
            int gc = C0 - 4 + 4 * f;
            float4 v = make_float4(0.f, 0.f, 0.f, 0.f);
            if ((unsigned)gr < (unsigned)IMG && (unsigned)gc < (unsigned)IMG)
                v = *reinterpret_cast<const float4*>(in + gr * IMG + gc);
            *reinterpret_cast<float4*>(&sm[r][4 * f]) = v;
        }
    }
    __syncthreads();

    const int wid   = tid >> 5;
    const int lane  = tid & 31;
    const int rbase = wid * 32;        // smem row base for this warp
    const int c2    = 2 * lane;        // even -> 8B-aligned LDS.64

    ull_t acc[7];
#pragma unroll
    for (int i = 0; i < 7; ++i) acc[i] = 0ull;

    float* outp = out + (size_t)plane * (IMG * IMG);

#pragma unroll
    for (int r = 0; r < 38; ++r) {
        const float2* row = reinterpret_cast<const float2*>(&sm[rbase + r][c2]);
        float2 B0 = row[0];
        float2 B1 = row[1];
        float2 B2 = row[2];
        float2 B3 = row[3];
        float2 B4 = row[4];

        // Pairs Q[k] = (v[c2+1+k], v[c2+2+k]), k=0..6
        ull_t Q[7];
        F2U u1, u2, u3;
        u1.f = B1; u2.f = B2; u3.f = B3;
        Q[1] = u1.u;                 // free: aligned pair
        Q[3] = u2.u;
        Q[5] = u3.u;
        Q[0] = pk2(B0.y, B1.x);      // cross pairs
        Q[2] = pk2(B1.y, B2.x);
        Q[4] = pk2(B2.y, B3.x);
        Q[6] = pk2(B3.y, B4.x);

#pragma unroll
        for (int j = 0; j < 7; ++j) {
            int y = r - j;                       // output row fed by this input row
            if (y < 0 || y >= 32) continue;      // compile-time dead-code
            ull_t* a = &acc[y % 7];
#pragma unroll
            for (int k = 0; k < 7; ++k)
                fma2(*a, Q[k], WW[j * 7 + k]);
        }

        if (r >= 6) {                            // output row r-6 is complete
            int y  = r - 6;
            int gy = R0 + rbase + y;
            *reinterpret_cast<ull_t*>(outp + gy * IMG + C0 + c2) = acc[y % 7];
            acc[y % 7] = 0ull;
        }
    }
}

extern "C" void kernel_launch(void* const* d_in, const int* in_sizes, int n_in,
                              void* d_out, int out_size) {
    const float* x      = (const float*)d_in[0];  // [16,64,256,256]
    const float* weight = (const float*)d_in[1];  // [64,64,7,7]
    const float* noise  = (const float*)d_in[2];  // scalar
    const float* eps    = (const float*)d_in[3];  // [7,7]
    float* out = (float*)d_out;

    prep_weights<<<1, NCH>>>(weight, noise, eps);

    dim3 grid(IMG / TILE_W, IMG / TILE_H, 16 * NCH);   // (4, 2, 1024)
    conv7x7_kernel<<<grid, 128>>>(x, out);
}